// round 2
// baseline (speedup 1.0000x reference)
#include <cuda_runtime.h>
#include <math.h>

// Problem constants
#define B_   1024
#define T_   64
#define H_   512
#define V_   1024
#define G_   100
#define FH_  2048   // 4*H

// ---------------- persistent device scratch (no allocations allowed) ----------------
__device__ float g_h[2][B_ * H_];           // ping-pong hidden state
__device__ float g_c[B_ * H_];              // cell state (updated in place)
__device__ int   g_tok[B_];                 // current token per row
__device__ float g_bcomb[FH_];              // b_ih + b_hh
__device__ float g_WihT[(size_t)V_ * FH_];  // W_ih transposed: [V][4H]  (one-hot gather rows)
__device__ float g_W1T[H_ * G_];            // W1 transposed: [H][GEN]
__device__ float g_W2T[G_ * V_];            // W2 transposed: [GEN][V]

// ---------------- init: h0/c0, tok0 from onehots[:,0,:], combined bias ----------------
__global__ void init_kernel(const float* __restrict__ inp,
                            const float* __restrict__ onehots,
                            const float* __restrict__ Wh, const float* __restrict__ bh,
                            const float* __restrict__ Wc, const float* __restrict__ bc,
                            const float* __restrict__ bih, const float* __restrict__ bhh) {
    int b = blockIdx.x;
    float x = inp[b];
    for (int j = threadIdx.x; j < H_; j += blockDim.x) {
        g_h[0][b * H_ + j] = x * Wh[j] + bh[j];
        g_c[b * H_ + j]    = x * Wc[j] + bc[j];
    }
    const float* oh = onehots + (size_t)b * T_ * V_;  // t = 0 slice
    for (int v = threadIdx.x; v < V_; v += blockDim.x)
        if (oh[v] > 0.5f) g_tok[b] = v;   // exactly one per row
    if (b == 0)
        for (int j = threadIdx.x; j < FH_; j += blockDim.x)
            g_bcomb[j] = bih[j] + bhh[j];
}

// ---------------- generic transpose into one of the scratch weights ----------------
__global__ void transpose_kernel(const float* __restrict__ in, int rows, int cols, int which) {
    float* out = (which == 0) ? g_WihT : (which == 1) ? g_W1T : g_W2T;
    __shared__ float tile[32][33];
    int c0 = blockIdx.x * 32, r0 = blockIdx.y * 32;
    int tx = threadIdx.x, ty = threadIdx.y;  // 32 x 8
    for (int i = ty; i < 32; i += 8) {
        int r = r0 + i, c = c0 + tx;
        if (r < rows && c < cols) tile[i][tx] = in[(size_t)r * cols + c];
    }
    __syncthreads();
    for (int i = ty; i < 32; i += 8) {
        int r = c0 + i, c = r0 + tx;
        if (r < cols && c < rows) out[(size_t)r * rows + c] = tile[tx][i];
    }
}

// ---------------- gates: fused GEMM (h @ W_hh^T, all 4 gates) + one-hot gather + LSTM update ----------------
// Tile: BM=64 rows x BN=64 h-cols (=> 256 gate-cols), K=512, 256 threads,
// each thread computes 4 rows x 4 cols x 4 gates = 64 fp32 accumulators.
#define BM 64
#define BN 64
#define BK 32
#define AST 68
#define BST 68

__global__ __launch_bounds__(256) void gates_kernel(const float* __restrict__ Whh, int parity) {
    __shared__ float As[BK][AST];        // [k][m]
    __shared__ float Bs[4][BK][BST];     // [gate][k][n]
    const float* __restrict__ hin = g_h[parity];
    float* __restrict__ hout = g_h[parity ^ 1];
    int m0 = blockIdx.x * BM;
    int n0 = blockIdx.y * BN;
    int tid = threadIdx.x;
    int row_t = tid >> 4;   // 0..15
    int col_t = tid & 15;   // 0..15

    float acc[4][4][4];
    #pragma unroll
    for (int g = 0; g < 4; g++)
        #pragma unroll
        for (int i = 0; i < 4; i++)
            #pragma unroll
            for (int j = 0; j < 4; j++) acc[g][i][j] = 0.0f;

    for (int kt = 0; kt < H_; kt += BK) {
        // A tile: 64 rows x 32 k  (h is row-major, K-contiguous) -> transposed store
        #pragma unroll
        for (int s = 0; s < 2; s++) {
            int e = tid + 256 * s;
            int ml = e >> 3, k4 = (e & 7) << 2;
            float4 v = *(const float4*)&hin[(size_t)(m0 + ml) * H_ + kt + k4];
            As[k4 + 0][ml] = v.x; As[k4 + 1][ml] = v.y;
            As[k4 + 2][ml] = v.z; As[k4 + 3][ml] = v.w;
        }
        // B tiles: 4 gates x 64 n x 32 k  (W_hh row-major [4H][H], K-contiguous)
        #pragma unroll
        for (int s = 0; s < 8; s++) {
            int e = tid + 256 * s;
            int rl = e >> 3, k4 = (e & 7) << 2;
            int g = rl >> 6, nl = rl & 63;
            float4 v = *(const float4*)&Whh[(size_t)(g * H_ + n0 + nl) * H_ + kt + k4];
            Bs[g][k4 + 0][nl] = v.x; Bs[g][k4 + 1][nl] = v.y;
            Bs[g][k4 + 2][nl] = v.z; Bs[g][k4 + 3][nl] = v.w;
        }
        __syncthreads();

        #pragma unroll
        for (int k = 0; k < BK; k++) {
            float4 a4 = *(const float4*)&As[k][row_t * 4];
            float av[4] = {a4.x, a4.y, a4.z, a4.w};
            #pragma unroll
            for (int g = 0; g < 4; g++) {
                float4 b4 = *(const float4*)&Bs[g][k][col_t * 4];
                float bv[4] = {b4.x, b4.y, b4.z, b4.w};
                #pragma unroll
                for (int i = 0; i < 4; i++)
                    #pragma unroll
                    for (int j = 0; j < 4; j++)
                        acc[g][i][j] += av[i] * bv[j];
            }
        }
        __syncthreads();
    }

    // Epilogue: one-hot gather (W_ihT row of current token) + bias + LSTM cell update
    #pragma unroll
    for (int i = 0; i < 4; i++) {
        int m = m0 + row_t * 4 + i;
        const float* wx = &g_WihT[(size_t)g_tok[m] * FH_];
        #pragma unroll
        for (int j = 0; j < 4; j++) {
            int n = n0 + col_t * 4 + j;
            float gi = acc[0][i][j] + wx[n]          + g_bcomb[n];
            float gf = acc[1][i][j] + wx[H_ + n]     + g_bcomb[H_ + n];
            float gg = acc[2][i][j] + wx[2 * H_ + n] + g_bcomb[2 * H_ + n];
            float go = acc[3][i][j] + wx[3 * H_ + n] + g_bcomb[3 * H_ + n];
            float si = 1.0f / (1.0f + expf(-gi));
            float sf = 1.0f / (1.0f + expf(-gf));
            float so = 1.0f / (1.0f + expf(-go));
            size_t idx = (size_t)m * H_ + n;
            float cn = sf * g_c[idx] + si * tanhf(gg);
            float hn = so * tanhf(cn);
            g_c[idx] = cn;
            hout[idx] = hn;
        }
    }
}

// ---------------- head: r = relu(h@W1^T+b1); logits = r@W2^T+b2; log_softmax; argmax -> tok; write out ----------------
#define HR 8
__global__ __launch_bounds__(256) void head_kernel(const float* __restrict__ b1,
                                                   const float* __restrict__ b2,
                                                   int parity, float* __restrict__ out) {
    // buf aliases: phase 1-2 uses it as sh_h[HR][H_] (4096 floats); phase 3+ as sh_lg[HR][V_] (8192 floats)
    __shared__ float buf[HR * V_];
    __shared__ float sh_r[HR][G_ + 4];
    __shared__ float red_v[8]; __shared__ int red_i[8]; __shared__ float red_s[8];
    __shared__ float s_max; __shared__ float s_sum;

    float (*sh_h)[H_] = (float (*)[H_])buf;
    float (*sh_lg)[V_] = (float (*)[V_])buf;

    const float* __restrict__ h = g_h[parity ^ 1];   // the h gates_kernel just wrote
    int row0 = blockIdx.x * HR;
    int tid = threadIdx.x;

    // load 8 h rows to smem
    for (int e = tid; e < HR * H_ / 4; e += 256) {
        int rr = e >> 7;      // H_/4 = 128 float4 per row
        int q = e & 127;
        float4 v = *(const float4*)&h[(size_t)(row0 + rr) * H_ + q * 4];
        *(float4*)&sh_h[rr][q * 4] = v;
    }
    __syncthreads();

    // r = relu(h @ W1^T + b1) : 100 threads, 8 rows each
    if (tid < G_) {
        float acc[HR];
        #pragma unroll
        for (int rr = 0; rr < HR; rr++) acc[rr] = 0.0f;
        for (int k = 0; k < H_; k++) {
            float w = g_W1T[k * G_ + tid];
            #pragma unroll
            for (int rr = 0; rr < HR; rr++) acc[rr] += w * sh_h[rr][k];
        }
        float bb = b1[tid];
        #pragma unroll
        for (int rr = 0; rr < HR; rr++) sh_r[rr][tid] = fmaxf(acc[rr] + bb, 0.0f);
    }
    __syncthreads();

    // logits = r @ W2^T + b2 : each thread 4 vocab cols x 8 rows (overwrites sh_h region; no longer read)
    #pragma unroll
    for (int s = 0; s < 4; s++) {
        int v = tid + 256 * s;
        float acc[HR];
        #pragma unroll
        for (int rr = 0; rr < HR; rr++) acc[rr] = 0.0f;
        for (int k = 0; k < G_; k++) {
            float w = g_W2T[k * V_ + v];
            #pragma unroll
            for (int rr = 0; rr < HR; rr++) acc[rr] += w * sh_r[rr][k];
        }
        float bb = b2[v];
        #pragma unroll
        for (int rr = 0; rr < HR; rr++) sh_lg[rr][v] = acc[rr] + bb;
    }
    __syncthreads();

    int lane = tid & 31, wid = tid >> 5;
    for (int rr = 0; rr < HR; rr++) {
        float4 xv = *(const float4*)&sh_lg[rr][tid * 4];
        float x[4] = {xv.x, xv.y, xv.z, xv.w};
        // argmax with jax tie rule (lowest index wins)
        float m = x[0]; int mi = tid * 4;
        #pragma unroll
        for (int s = 1; s < 4; s++)
            if (x[s] > m) { m = x[s]; mi = tid * 4 + s; }
        #pragma unroll
        for (int o = 16; o > 0; o >>= 1) {
            float om = __shfl_down_sync(0xffffffffu, m, o);
            int oi = __shfl_down_sync(0xffffffffu, mi, o);
            if (om > m || (om == m && oi < mi)) { m = om; mi = oi; }
        }
        if (lane == 0) { red_v[wid] = m; red_i[wid] = mi; }
        __syncthreads();
        if (tid == 0) {
            float bm = red_v[0]; int bi = red_i[0];
            #pragma unroll
            for (int w = 1; w < 8; w++)
                if (red_v[w] > bm || (red_v[w] == bm && red_i[w] < bi)) { bm = red_v[w]; bi = red_i[w]; }
            s_max = bm;
            g_tok[row0 + rr] = bi;   // feedback token for next step
        }
        __syncthreads();
        float lm = s_max;
        float sum = 0.0f;
        #pragma unroll
        for (int s = 0; s < 4; s++) sum += expf(x[s] - lm);
        #pragma unroll
        for (int o = 16; o > 0; o >>= 1) sum += __shfl_down_sync(0xffffffffu, sum, o);
        if (lane == 0) red_s[wid] = sum;
        __syncthreads();
        if (tid == 0) {
            float t = 0.0f;
            #pragma unroll
            for (int w = 0; w < 8; w++) t += red_s[w];
            s_sum = t;
        }
        __syncthreads();
        float lse = lm + logf(s_sum);
        float4 ov = make_float4(x[0] - lse, x[1] - lse, x[2] - lse, x[3] - lse);
        *(float4*)&out[(size_t)(row0 + rr) * V_ + tid * 4] = ov;
        __syncthreads();
    }
}

// ---------------- launch ----------------
extern "C" void kernel_launch(void* const* d_in, const int* in_sizes, int n_in,
                              void* d_out, int out_size) {
    // metadata order: input, onehots, digits, teacher, Wh, bh, Wc, bc, W_ih, W_hh, b_ih, b_hh, W1, b1, W2, b2
    int wi = 4;
    if (n_in >= 4 && in_sizes[3] != 1) wi = 3;   // defensive: teacher scalar omitted
    const float* input   = (const float*)d_in[0];
    const float* onehots = (const float*)d_in[1];
    const float* Wh  = (const float*)d_in[wi + 0];
    const float* bh  = (const float*)d_in[wi + 1];
    const float* Wc  = (const float*)d_in[wi + 2];
    const float* bc  = (const float*)d_in[wi + 3];
    const float* Wih = (const float*)d_in[wi + 4];
    const float* Whh = (const float*)d_in[wi + 5];
    const float* bih = (const float*)d_in[wi + 6];
    const float* bhh = (const float*)d_in[wi + 7];
    const float* W1  = (const float*)d_in[wi + 8];
    const float* b1  = (const float*)d_in[wi + 9];
    const float* W2  = (const float*)d_in[wi + 10];
    const float* b2  = (const float*)d_in[wi + 11];
    float* out = (float*)d_out;
    (void)out_size;

    init_kernel<<<B_, 256>>>(input, onehots, Wh, bh, Wc, bc, bih, bhh);
    dim3 tb(32, 8);
    transpose_kernel<<<dim3(V_ / 32, FH_ / 32), tb>>>(Wih, FH_, V_, 0);
    transpose_kernel<<<dim3((H_ + 31) / 32, (G_ + 31) / 32), tb>>>(W1, G_, H_, 1);
    transpose_kernel<<<dim3((G_ + 31) / 32, (V_ + 31) / 32), tb>>>(W2, V_, G_, 2);

    for (int t = 0; t < T_; t++) {
        gates_kernel<<<dim3(B_ / BM, H_ / BN), 256>>>(Whh, t & 1);
        head_kernel<<<B_ / HR, 256>>>(b1, b2, t & 1, out + (size_t)t * B_ * V_);
    }
}

// round 5
// speedup vs baseline: 1.2927x; 1.2927x over previous
#include <cuda_runtime.h>
#include <cuda_bf16.h>
#include <math.h>
#include <stdint.h>

// Problem constants
#define B_   1024
#define T_   64
#define H_   512
#define V_   1024
#define G_   100
#define FH_  2048   // 4*H

// GEMM tiling
#define MT_   8       // M tiles of 128 rows
#define NT_   16      // N tiles of 128 reordered cols
#define BK_   32      // k per chunk
#define NK_   16      // 512 / 32
#define ROWB_ 80      // padded smem row stride bytes (32 bf16 = 64B + 16B pad)
#define PLANE_B 10240 // 128 rows * 80B
#define STAGE_B 61440 // 6 planes (3 A + 3 B)
#define SMEM_DYN (2 * STAGE_B)

// ---------------- persistent device scratch ----------------
__device__ float g_h[2][B_ * H_];                    // ping-pong fp32 hidden
__device__ float g_c[B_ * H_];                       // cell state
__device__ int   g_tok[B_];                          // current token per row
__device__ float g_bR[FH_];                          // reordered combined bias
__device__ float g_WihR[(size_t)V_ * FH_];           // reordered one-hot gather [V][n']
__device__ __nv_bfloat16 g_Bs[3][(size_t)FH_ * H_];  // Whh bf16x3 planes, reordered rows [n'][k]
__device__ float g_W1T[H_ * G_];
__device__ float g_W2T[G_ * V_];

// n' = nt*128 + 4*jl + gate  <->  original gate row gr = gate*512 + nt*32 + jl
__device__ __forceinline__ int np_to_gr(int np) {
    int nt = np >> 7, rem = np & 127, jl = rem >> 2, gg = rem & 3;
    return gg * 512 + nt * 32 + jl;
}

__device__ __forceinline__ uint32_t smem_u32(const void* p) {
    uint32_t a;
    asm("{ .reg .u64 t; cvta.to.shared.u64 t, %1; cvt.u32.u64 %0, t; }" : "=r"(a) : "l"(p));
    return a;
}

#define CP16(dst, src) \
    asm volatile("cp.async.cg.shared.global [%0], [%1], 16;" :: "r"(dst), "l"(src) : "memory")
#define CP_WAIT_ALL() asm volatile("cp.async.wait_all;" ::: "memory")

#define MMA16816(d0, d1, d2, d3, a0, a1, a2, a3, b0, b1) \
    asm volatile("mma.sync.aligned.m16n8k16.row.col.f32.bf16.bf16.f32 " \
                 "{%0,%1,%2,%3}, {%4,%5,%6,%7}, {%8,%9}, {%0,%1,%2,%3};" \
                 : "+f"(d0), "+f"(d1), "+f"(d2), "+f"(d3) \
                 : "r"(a0), "r"(a1), "r"(a2), "r"(a3), "r"(b0), "r"(b1))

__device__ __forceinline__ void split3(float v, __nv_bfloat16& s0, __nv_bfloat16& s1, __nv_bfloat16& s2) {
    s0 = __float2bfloat16_rn(v);
    float r1 = v - __bfloat162float(s0);
    s1 = __float2bfloat16_rn(r1);
    float r2 = r1 - __bfloat162float(s1);
    s2 = __float2bfloat16_rn(r2);
}
__device__ __forceinline__ uint32_t pack2(__nv_bfloat16 a, __nv_bfloat16 b) {
    __nv_bfloat162 h2; h2.x = a; h2.y = b;
    return *(uint32_t*)&h2;
}

// ---------------- init: h0/c0, tok0 ----------------
__global__ void init_kernel(const float* __restrict__ inp,
                            const float* __restrict__ onehots,
                            const float* __restrict__ Wh, const float* __restrict__ bh,
                            const float* __restrict__ Wc, const float* __restrict__ bc) {
    int b = blockIdx.x;
    float x = inp[b];
    for (int j = threadIdx.x; j < H_; j += blockDim.x) {
        g_h[0][b * H_ + j] = x * Wh[j] + bh[j];
        g_c[b * H_ + j]    = x * Wc[j] + bc[j];
    }
    const float* oh = onehots + (size_t)b * T_ * V_;  // t = 0 slice
    for (int v = threadIdx.x; v < V_; v += blockDim.x)
        if (oh[v] > 0.5f) g_tok[b] = v;
}

// ---------------- prep: Whh -> 3 bf16 planes (reordered [n'][k]) + combined bias ----------------
__global__ void prep_B(const float* __restrict__ Whh,
                       const float* __restrict__ bih, const float* __restrict__ bhh) {
    int np = blockIdx.x;
    int gr = np_to_gr(np);
    if (threadIdx.x == 0) g_bR[np] = bih[gr] + bhh[gr];
    for (int k = threadIdx.x; k < H_; k += blockDim.x) {
        __nv_bfloat16 s0, s1, s2;
        split3(Whh[(size_t)gr * H_ + k], s0, s1, s2);
        size_t o = (size_t)np * H_ + k;
        g_Bs[0][o] = s0; g_Bs[1][o] = s1; g_Bs[2][o] = s2;
    }
}

// ---------------- prep: reordered one-hot gather table ----------------
__global__ void prep_Wih(const float* __restrict__ Wih) {
    int v = blockIdx.x;
    for (int np = threadIdx.x; np < FH_; np += blockDim.x) {
        int gr = np_to_gr(np);
        g_WihR[(size_t)v * FH_ + np] = Wih[(size_t)gr * V_ + v];
    }
}

// ---------------- transpose for head weights ----------------
__global__ void transpose_kernel(const float* __restrict__ in, int rows, int cols, int which) {
    float* out = (which == 1) ? g_W1T : g_W2T;
    __shared__ float tile[32][33];
    int c0 = blockIdx.x * 32, r0 = blockIdx.y * 32;
    int tx = threadIdx.x, ty = threadIdx.y;
    for (int i = ty; i < 32; i += 8) {
        int r = r0 + i, c = c0 + tx;
        if (r < rows && c < cols) tile[i][tx] = in[(size_t)r * cols + c];
    }
    __syncthreads();
    for (int i = ty; i < 32; i += 8) {
        int r = c0 + i, c = r0 + tx;
        if (r < cols && c < rows) out[(size_t)r * rows + c] = tile[tx][i];
    }
}

// ---------------- gates: mma.sync bf16x3 GEMM + LSTM epilogue ----------------
__global__ __launch_bounds__(256, 1) void gates_kernel(int parity) {
    extern __shared__ char smem[];
    int tid = threadIdx.x, wid = tid >> 5, lane = tid & 31;
    int gq = lane >> 2, tq = lane & 3;      // groupID, threadID-in-group
    int mt = blockIdx.x, nt = blockIdx.y;
    int mwarp = (wid >> 1) * 32;            // 4 warps along M
    int nwarp = (wid & 1) * 64;             // 2 warps along N
    const float* __restrict__ hin = g_h[parity];
    float* __restrict__ hout = g_h[parity ^ 1];
    uint32_t smem_base = smem_u32(smem);

    float acc[2][8][4];
    #pragma unroll
    for (int mi = 0; mi < 2; mi++)
        #pragma unroll
        for (int ni = 0; ni < 8; ni++)
            #pragma unroll
            for (int q = 0; q < 4; q++) acc[mi][ni][q] = 0.0f;

    float4 Areg[4];

    // ---- helpers as macros over locals ----
    #define LDG_A(kc) do { \
        _Pragma("unroll") \
        for (int s = 0; s < 4; s++) { \
            int e = tid + 256 * s; \
            int row = e >> 3, cq = e & 7; \
            Areg[s] = *(const float4*)&hin[(size_t)(mt * 128 + row) * H_ + (kc) * BK_ + cq * 4]; \
        } \
    } while (0)

    #define STS_A(st) do { \
        char* base = smem + (st) * STAGE_B; \
        _Pragma("unroll") \
        for (int s = 0; s < 4; s++) { \
            int e = tid + 256 * s; \
            int row = e >> 3, cq = e & 7; \
            float vv[4] = {Areg[s].x, Areg[s].y, Areg[s].z, Areg[s].w}; \
            __nv_bfloat16 p0[4], p1[4], p2[4]; \
            _Pragma("unroll") \
            for (int q = 0; q < 4; q++) split3(vv[q], p0[q], p1[q], p2[q]); \
            char* dst = base + row * ROWB_ + cq * 8; \
            *(uint2*)(dst)                = make_uint2(pack2(p0[0], p0[1]), pack2(p0[2], p0[3])); \
            *(uint2*)(dst + PLANE_B)      = make_uint2(pack2(p1[0], p1[1]), pack2(p1[2], p1[3])); \
            *(uint2*)(dst + 2 * PLANE_B)  = make_uint2(pack2(p2[0], p2[1]), pack2(p2[2], p2[3])); \
        } \
    } while (0)

    #define LOAD_B(kc, st) do { \
        uint32_t bb = smem_base + (st) * STAGE_B + 3 * PLANE_B; \
        _Pragma("unroll") \
        for (int s = 0; s < 6; s++) { \
            int e = tid + 256 * s; \
            int p = e >> 9, rem = e & 511; \
            int n = rem >> 2, q = rem & 3; \
            const __nv_bfloat16* src = &g_Bs[p][(size_t)(nt * 128 + n) * H_ + (kc) * BK_ + q * 8]; \
            CP16(bb + p * PLANE_B + n * ROWB_ + q * 16, src); \
        } \
    } while (0)

    #define COMPUTE(st) do { \
        const char* base = smem + (st) * STAGE_B; \
        _Pragma("unroll") \
        for (int kk = 0; kk < 2; kk++) { \
            _Pragma("unroll") \
            for (int pb = 0; pb < 3; pb++) { \
                uint32_t bf[8][2]; \
                _Pragma("unroll") \
                for (int ni = 0; ni < 8; ni++) { \
                    const char* bp = base + 3 * PLANE_B + pb * PLANE_B \
                                   + (nwarp + ni * 8 + gq) * ROWB_ + (kk * 16 + 2 * tq) * 2; \
                    bf[ni][0] = *(const uint32_t*)bp; \
                    bf[ni][1] = *(const uint32_t*)(bp + 16); \
                } \
                int npa = 3 - pb; \
                _Pragma("unroll") \
                for (int pa = 0; pa < 3; pa++) { \
                    if (pa >= npa) break; \
                    _Pragma("unroll") \
                    for (int mi = 0; mi < 2; mi++) { \
                        const char* ap = base + pa * PLANE_B \
                                       + (mwarp + mi * 16 + gq) * ROWB_ + (kk * 16 + 2 * tq) * 2; \
                        uint32_t a0 = *(const uint32_t*)ap; \
                        uint32_t a1 = *(const uint32_t*)(ap + 8 * ROWB_); \
                        uint32_t a2 = *(const uint32_t*)(ap + 16); \
                        uint32_t a3 = *(const uint32_t*)(ap + 8 * ROWB_ + 16); \
                        _Pragma("unroll") \
                        for (int ni = 0; ni < 8; ni++) \
                            MMA16816(acc[mi][ni][0], acc[mi][ni][1], acc[mi][ni][2], acc[mi][ni][3], \
                                     a0, a1, a2, a3, bf[ni][0], bf[ni][1]); \
                    } \
                } \
            } \
        } \
    } while (0)

    // ---- pipeline ----
    LDG_A(0);
    LOAD_B(0, 0);
    STS_A(0);
    CP_WAIT_ALL();
    __syncthreads();

    for (int kc = 0; kc < NK_; kc++) {
        int cur = kc & 1, nxt = cur ^ 1;
        if (kc + 1 < NK_) { LDG_A(kc + 1); LOAD_B(kc + 1, nxt); }
        COMPUTE(cur);
        if (kc + 1 < NK_) STS_A(nxt);
        CP_WAIT_ALL();
        __syncthreads();
    }

    // ---- epilogue: assemble (i,f,g,o), LSTM update ----
    #pragma unroll
    for (int mi = 0; mi < 2; mi++) {
        int r0 = mwarp + mi * 16 + gq;
        int m0 = mt * 128 + r0;
        int m1 = m0 + 8;
        int tok0 = g_tok[m0], tok1 = g_tok[m1];
        const float* w0 = g_WihR + (size_t)tok0 * FH_;
        const float* w1 = g_WihR + (size_t)tok1 * FH_;
        #pragma unroll
        for (int ni = 0; ni < 8; ni++) {
            float c0 = acc[mi][ni][0], c1 = acc[mi][ni][1];
            float c2 = acc[mi][ni][2], c3 = acc[mi][ni][3];
            float gv0 = __shfl_xor_sync(0xffffffffu, c0, 1);
            float ov0 = __shfl_xor_sync(0xffffffffu, c1, 1);
            float gv1 = __shfl_xor_sync(0xffffffffu, c2, 1);
            float ov1 = __shfl_xor_sync(0xffffffffu, c3, 1);
            if (!(lane & 1)) {
                int colq = nt * 128 + nwarp + ni * 8 + 2 * tq;  // 4-aligned (tq even)
                float4 b4 = *(const float4*)&g_bR[colq];
                float4 wa = *(const float4*)&w0[colq];
                float4 wb = *(const float4*)&w1[colq];
                int j = colq >> 2;   // global h col 0..511
                {
                    float gi = c0 + wa.x + b4.x;
                    float gf = c1 + wa.y + b4.y;
                    float gg = gv0 + wa.z + b4.z;
                    float go = ov0 + wa.w + b4.w;
                    float si = 1.0f / (1.0f + expf(-gi));
                    float sf = 1.0f / (1.0f + expf(-gf));
                    float so = 1.0f / (1.0f + expf(-go));
                    size_t idx = (size_t)m0 * H_ + j;
                    float cn = sf * g_c[idx] + si * tanhf(gg);
                    g_c[idx] = cn;
                    hout[idx] = so * tanhf(cn);
                }
                {
                    float gi = c2 + wb.x + b4.x;
                    float gf = c3 + wb.y + b4.y;
                    float gg = gv1 + wb.z + b4.z;
                    float go = ov1 + wb.w + b4.w;
                    float si = 1.0f / (1.0f + expf(-gi));
                    float sf = 1.0f / (1.0f + expf(-gf));
                    float so = 1.0f / (1.0f + expf(-go));
                    size_t idx = (size_t)m1 * H_ + j;
                    float cn = sf * g_c[idx] + si * tanhf(gg);
                    g_c[idx] = cn;
                    hout[idx] = so * tanhf(cn);
                }
            }
        }
    }
}

// ---------------- head: relu(h@W1T+b1)@W2T+b2 -> log_softmax, argmax -> tok ----------------
#define HR 8
__global__ __launch_bounds__(256) void head_kernel(const float* __restrict__ b1,
                                                   const float* __restrict__ b2,
                                                   int parity, float* __restrict__ out) {
    __shared__ float buf[HR * V_];
    __shared__ float sh_r[HR][G_ + 4];
    __shared__ float red_v[8]; __shared__ int red_i[8]; __shared__ float red_s[8];
    __shared__ float s_max; __shared__ float s_sum;

    float (*sh_h)[H_] = (float (*)[H_])buf;
    float (*sh_lg)[V_] = (float (*)[V_])buf;

    const float* __restrict__ h = g_h[parity ^ 1];
    int row0 = blockIdx.x * HR;
    int tid = threadIdx.x;

    for (int e = tid; e < HR * H_ / 4; e += 256) {
        int rr = e >> 7;
        int q = e & 127;
        *(float4*)&sh_h[rr][q * 4] = *(const float4*)&h[(size_t)(row0 + rr) * H_ + q * 4];
    }
    __syncthreads();

    if (tid < 2 * G_) {
        int col = tid % G_;
        int half = tid / G_;
        float acc[4] = {0.f, 0.f, 0.f, 0.f};
        for (int k = 0; k < H_; k++) {
            float w = g_W1T[k * G_ + col];
            #pragma unroll
            for (int r2 = 0; r2 < 4; r2++) acc[r2] += w * sh_h[half * 4 + r2][k];
        }
        float bb = b1[col];
        #pragma unroll
        for (int r2 = 0; r2 < 4; r2++) sh_r[half * 4 + r2][col] = fmaxf(acc[r2] + bb, 0.0f);
    }
    __syncthreads();

    #pragma unroll
    for (int s = 0; s < 4; s++) {
        int v = tid + 256 * s;
        float acc[HR];
        #pragma unroll
        for (int rr = 0; rr < HR; rr++) acc[rr] = 0.0f;
        for (int k = 0; k < G_; k++) {
            float w = g_W2T[k * V_ + v];
            #pragma unroll
            for (int rr = 0; rr < HR; rr++) acc[rr] += w * sh_r[rr][k];
        }
        float bb = b2[v];
        #pragma unroll
        for (int rr = 0; rr < HR; rr++) sh_lg[rr][v] = acc[rr] + bb;
    }
    __syncthreads();

    int lane = tid & 31, wid = tid >> 5;
    for (int rr = 0; rr < HR; rr++) {
        float4 xv = *(const float4*)&sh_lg[rr][tid * 4];
        float x[4] = {xv.x, xv.y, xv.z, xv.w};
        float m = x[0]; int mi = tid * 4;
        #pragma unroll
        for (int s = 1; s < 4; s++)
            if (x[s] > m) { m = x[s]; mi = tid * 4 + s; }
        #pragma unroll
        for (int o = 16; o > 0; o >>= 1) {
            float om = __shfl_down_sync(0xffffffffu, m, o);
            int oi = __shfl_down_sync(0xffffffffu, mi, o);
            if (om > m || (om == m && oi < mi)) { m = om; mi = oi; }
        }
        if (lane == 0) { red_v[wid] = m; red_i[wid] = mi; }
        __syncthreads();
        if (tid == 0) {
            float bm = red_v[0]; int bi = red_i[0];
            #pragma unroll
            for (int w = 1; w < 8; w++)
                if (red_v[w] > bm || (red_v[w] == bm && red_i[w] < bi)) { bm = red_v[w]; bi = red_i[w]; }
            s_max = bm;
            g_tok[row0 + rr] = bi;
        }
        __syncthreads();
        float lm = s_max;
        float sum = 0.0f;
        #pragma unroll
        for (int s = 0; s < 4; s++) sum += expf(x[s] - lm);
        #pragma unroll
        for (int o = 16; o > 0; o >>= 1) sum += __shfl_down_sync(0xffffffffu, sum, o);
        if (lane == 0) red_s[wid] = sum;
        __syncthreads();
        if (tid == 0) {
            float t = 0.0f;
            #pragma unroll
            for (int w = 0; w < 8; w++) t += red_s[w];
            s_sum = t;
        }
        __syncthreads();
        float lse = lm + logf(s_sum);
        float4 ov = make_float4(x[0] - lse, x[1] - lse, x[2] - lse, x[3] - lse);
        *(float4*)&out[(size_t)(row0 + rr) * V_ + tid * 4] = ov;
        __syncthreads();
    }
}

// ---------------- launch ----------------
extern "C" void kernel_launch(void* const* d_in, const int* in_sizes, int n_in,
                              void* d_out, int out_size) {
    int wi = 4;
    if (n_in >= 4 && in_sizes[3] != 1) wi = 3;
    const float* input   = (const float*)d_in[0];
    const float* onehots = (const float*)d_in[1];
    const float* Wh  = (const float*)d_in[wi + 0];
    const float* bh  = (const float*)d_in[wi + 1];
    const float* Wc  = (const float*)d_in[wi + 2];
    const float* bc  = (const float*)d_in[wi + 3];
    const float* Wih = (const float*)d_in[wi + 4];
    const float* Whh = (const float*)d_in[wi + 5];
    const float* bih = (const float*)d_in[wi + 6];
    const float* bhh = (const float*)d_in[wi + 7];
    const float* W1  = (const float*)d_in[wi + 8];
    const float* b1  = (const float*)d_in[wi + 9];
    const float* W2  = (const float*)d_in[wi + 10];
    const float* b2  = (const float*)d_in[wi + 11];
    float* out = (float*)d_out;
    (void)out_size;

    static int smem_set = 0;
    if (!smem_set) {
        cudaFuncSetAttribute(gates_kernel, cudaFuncAttributeMaxDynamicSharedMemorySize, SMEM_DYN);
        smem_set = 1;
    }

    init_kernel<<<B_, 256>>>(input, onehots, Wh, bh, Wc, bc);
    prep_B<<<FH_, 128>>>(Whh, bih, bhh);
    prep_Wih<<<V_, 256>>>(Wih);
    dim3 tb(32, 8);
    transpose_kernel<<<dim3((H_ + 31) / 32, (G_ + 31) / 32), tb>>>(W1, G_, H_, 1);
    transpose_kernel<<<dim3((G_ + 31) / 32, (V_ + 31) / 32), tb>>>(W2, V_, G_, 2);

    for (int t = 0; t < T_; t++) {
        gates_kernel<<<dim3(MT_, NT_), 256, SMEM_DYN>>>(t & 1);
        head_kernel<<<B_ / HR, 256>>>(b1, b2, t & 1, out + (size_t)t * B_ * V_);
    }
}